// round 2
// baseline (speedup 1.0000x reference)
#include <cuda_runtime.h>

// Shapes (fixed for this problem):
//   x: (1, 384, 256), gamma/beta: (256), Wa/Wb: (32, 256),
//   Wo: (128, 1024), bo: (128)  ->  z: (1, 384, 384, 128) fp32
//
// Plan:
//   kA: layernorm(x) -> a[l][h] = xn.Wa^T, b[l][h] = xn.Wb^T   (384x32 each)
//   kB: U[i][o][d] = sum_c a[i][c] * Wo[o*1024 + c*32 + d]     (384x128x32)
//   kC: z[i][j][o] = bo[o] + sum_d U[i][o][d] * b[j][d]

#define L   384
#define DIM 256
#define H   32
#define OUT 128

__device__ float g_U[L * OUT * H];   // 6.29 MB scratch, [i][o][d]
__device__ float g_a[L * H];         // [l][h]
__device__ float g_b[L * H];         // [l][h]

// ---------------------------------------------------------------------------
// Kernel A: layernorm + two 256-dot GEMVs per row. 384 blocks x 256 threads.
// ---------------------------------------------------------------------------
__global__ void __launch_bounds__(256) kA(
    const float* __restrict__ x, const float* __restrict__ gamma,
    const float* __restrict__ beta, const float* __restrict__ Wa,
    const float* __restrict__ Wb)
{
    const int l = blockIdx.x;
    const int t = threadIdx.x;
    const int lane = t & 31, w = t >> 5;

    __shared__ float xn_sh[DIM];
    __shared__ float red[16];
    __shared__ float mu_s, rstd_s;

    float v = x[l * DIM + t];

    // block reduction: sum and sumsq
    float s = v, s2 = v * v;
    #pragma unroll
    for (int off = 16; off; off >>= 1) {
        s  += __shfl_down_sync(0xffffffffu, s,  off);
        s2 += __shfl_down_sync(0xffffffffu, s2, off);
    }
    if (lane == 0) { red[w] = s; red[8 + w] = s2; }
    __syncthreads();
    if (t == 0) {
        float S = 0.f, S2 = 0.f;
        #pragma unroll
        for (int k = 0; k < 8; k++) { S += red[k]; S2 += red[8 + k]; }
        float mu  = S * (1.0f / DIM);
        float var = S2 * (1.0f / DIM) - mu * mu;
        mu_s   = mu;
        rstd_s = rsqrtf(var + 1e-5f);
    }
    __syncthreads();

    xn_sh[t] = (v - mu_s) * rstd_s * gamma[t] + beta[t];
    __syncthreads();

    // 64 dot products of length 256: warp w handles outputs w*8 .. w*8+7
    #pragma unroll
    for (int q = 0; q < 8; q++) {
        int idx = w * 8 + q;                 // 0..63: 0..31 -> a, 32..63 -> b
        int h = idx & 31;
        const float* Wrow = (idx < 32 ? Wa : Wb) + h * DIM;
        float acc = 0.f;
        #pragma unroll
        for (int k = 0; k < 8; k++)
            acc += xn_sh[k * 32 + lane] * Wrow[k * 32 + lane];
        #pragma unroll
        for (int off = 16; off; off >>= 1)
            acc += __shfl_xor_sync(0xffffffffu, acc, off);
        if (lane == 0) {
            float* outp = (idx < 32) ? g_a : g_b;
            outp[l * H + h] = acc;
        }
    }
}

// ---------------------------------------------------------------------------
// Kernel B: U[i][o][d] = sum_c a[i][c] * Wo[o*1024 + c*32 + d]
// grid (48, 4): 8 i's per block, 32 o's per block (4 passes of 8 warps).
// lane = d (coalesced Wo reads and U writes).
// ---------------------------------------------------------------------------
__global__ void __launch_bounds__(256) kB(const float* __restrict__ Wo)
{
    const int it0 = blockIdx.x * 8;        // i tile base
    const int oc  = blockIdx.y;            // o chunk base / 32
    const int t = threadIdx.x;
    const int lane = t & 31, w = t >> 5;

    __shared__ float a_sh[8 * H];
    a_sh[t] = g_a[it0 * H + t];            // 256 floats, one per thread
    __syncthreads();

    #pragma unroll
    for (int p = 0; p < 4; p++) {
        const int o = oc * 32 + p * 8 + w;
        const float* wrow = Wo + o * (H * H) + lane;   // + c*32 per step
        float acc[8];
        #pragma unroll
        for (int i = 0; i < 8; i++) acc[i] = 0.f;
        #pragma unroll
        for (int c = 0; c < H; c++) {
            float wv = wrow[c * H];
            #pragma unroll
            for (int i = 0; i < 8; i++)
                acc[i] += a_sh[i * H + c] * wv;
        }
        #pragma unroll
        for (int i = 0; i < 8; i++)
            g_U[((it0 + i) * OUT + o) * H + lane] = acc[i];
    }
}

// ---------------------------------------------------------------------------
// Kernel C: z[i][j][o] = bo[o] + sum_d U[i][o][d] * b[j][d]
// grid (384, 6): one i, 64 j's per block. 256 threads = 8 warps.
// Thread: lane -> 4 o's (o = lane + 32*oo), warp -> 8 j's. 32 outputs/thread.
// U in smem with row stride 36 (conflict-free LDS.128); b reads broadcast.
// ---------------------------------------------------------------------------
#define USTRIDE 36
__global__ void __launch_bounds__(256) kC(
    const float* __restrict__ bo, float* __restrict__ z)
{
    const int i  = blockIdx.x;             // 0..383
    const int jt = blockIdx.y;             // 0..5  (64 j each)
    const int t = threadIdx.x;
    const int lane = t & 31, w = t >> 5;

    __shared__ float U_sh[OUT * USTRIDE];  // 18432 B
    __shared__ float b_sh[64 * H];         // 8192 B

    // Load U[i] : 4096 floats = 1024 float4, transposed pad-store
    {
        const float4* Ug4 = (const float4*)(g_U + i * (OUT * H));
        #pragma unroll
        for (int it = 0; it < 4; it++) {
            int idx = t + it * 256;        // float4 index
            int o = idx >> 3, d4 = idx & 7;
            float4 vv = Ug4[idx];
            *((float4*)&U_sh[o * USTRIDE + d4 * 4]) = vv;
        }
    }
    // Load b tile: 2048 floats = 512 float4, contiguous
    {
        const float4* bg4 = (const float4*)(g_b + jt * 64 * H);
        #pragma unroll
        for (int it = 0; it < 2; it++) {
            int idx = t + it * 256;
            ((float4*)b_sh)[idx] = bg4[idx];
        }
    }
    __syncthreads();

    const int j0 = w * 8;

    float acc[8][4];
    {
        float bov[4];
        #pragma unroll
        for (int oo = 0; oo < 4; oo++) bov[oo] = bo[lane + 32 * oo];
        #pragma unroll
        for (int jj = 0; jj < 8; jj++)
            #pragma unroll
            for (int oo = 0; oo < 4; oo++) acc[jj][oo] = bov[oo];
    }

    #pragma unroll 1
    for (int dc = 0; dc < H; dc += 8) {
        float u[4][8];
        #pragma unroll
        for (int oo = 0; oo < 4; oo++) {
            float4 v0 = *((const float4*)&U_sh[(lane + 32 * oo) * USTRIDE + dc]);
            float4 v1 = *((const float4*)&U_sh[(lane + 32 * oo) * USTRIDE + dc + 4]);
            u[oo][0]=v0.x; u[oo][1]=v0.y; u[oo][2]=v0.z; u[oo][3]=v0.w;
            u[oo][4]=v1.x; u[oo][5]=v1.y; u[oo][6]=v1.z; u[oo][7]=v1.w;
        }
        #pragma unroll
        for (int jj = 0; jj < 8; jj++) {
            float4 w0 = *((const float4*)&b_sh[(j0 + jj) * H + dc]);
            float4 w1 = *((const float4*)&b_sh[(j0 + jj) * H + dc + 4]);
            float bv[8];
            bv[0]=w0.x; bv[1]=w0.y; bv[2]=w0.z; bv[3]=w0.w;
            bv[4]=w1.x; bv[5]=w1.y; bv[6]=w1.z; bv[7]=w1.w;
            #pragma unroll
            for (int oo = 0; oo < 4; oo++)
                #pragma unroll
                for (int k = 0; k < 8; k++)
                    acc[jj][oo] += u[oo][k] * bv[k];
        }
    }

    // Write: z[(i*384 + jt*64 + j0 + jj)*128 + lane + 32*oo]
    long base = ((long)(i * L + jt * 64 + j0)) * OUT;
    #pragma unroll
    for (int jj = 0; jj < 8; jj++) {
        float* zp = z + base + (long)jj * OUT + lane;
        #pragma unroll
        for (int oo = 0; oo < 4; oo++)
            zp[32 * oo] = acc[jj][oo];
    }
}

// ---------------------------------------------------------------------------
extern "C" void kernel_launch(void* const* d_in, const int* in_sizes, int n_in,
                              void* d_out, int out_size)
{
    const float* x     = (const float*)d_in[0];
    const float* gamma = (const float*)d_in[1];
    const float* beta  = (const float*)d_in[2];
    const float* Wa    = (const float*)d_in[3];
    const float* Wb    = (const float*)d_in[4];
    const float* Wo    = (const float*)d_in[5];
    const float* bo    = (const float*)d_in[6];
    float* z = (float*)d_out;

    kA<<<L, 256>>>(x, gamma, beta, Wa, Wb);
    kB<<<dim3(48, 4), 256>>>(Wo);
    kC<<<dim3(L, 6), 256>>>(bo, z);
}